// round 10
// baseline (speedup 1.0000x reference)
#include <cuda_runtime.h>
#include <math.h>
#include <stdint.h>

// Problem constants (fixed by the reference)
#define Nn 20000
#define Ee 320000
#define Dd 128
#define Kk 8
#define Hh 64
#define Ll 3
#define FULL 0xffffffffu

#define TILES ((Nn + 127) / 128)      // 157
#define BPT 40                        // 32 agg blocks + 8 gemm blocks per tile

// -------- device scratch (static globals; no allocation) --------
__device__ float g_S[(size_t)Nn * Kk * Dd];   // 81.92 MB per-node weighted sums
__device__ float g_v[Kk * Dd];                // folded (W_enc*attn_l)/3
__device__ int   g_deg[Nn];
__device__ int   g_beg[Nn];
__device__ int   g_cur[Nn];
__device__ int   g_perm[Ee];
__device__ int   g_ctr;
__device__ unsigned g_done[TILES];            // per-tile agg completion counters

// ---------------------------------------------------------------
// K0: fold v[k][d] = (1/3)*sum_h W_enc[d,kH+h]*attn_l[k,h];
//     zero deg/ctr/done
// ---------------------------------------------------------------
__global__ void k_prep(const float* __restrict__ We, const float* __restrict__ al) {
    __shared__ float al_sh[Kk * Hh];
    int t = threadIdx.x;                // 1024 threads
    if (t < Kk * Hh) al_sh[t] = al[t];
    for (int i = t; i < Nn; i += 1024) g_deg[i] = 0;
    if (t < TILES) g_done[t] = 0u;
    if (t == 0) g_ctr = 0;
    __syncthreads();
    int k = t >> 7;
    int d = t & 127;
    const float* wrow = We + (size_t)d * (Kk * Hh) + k * Hh;
    const float* arow = al_sh + k * Hh;
    float s = 0.f;
#pragma unroll 8
    for (int h = 0; h < Hh; ++h) s = fmaf(wrow[h], arow[h], s);
    g_v[k * Dd + d] = s * (1.f / 3.f);
}

// ---------------------------------------------------------------
// K1: histogram of dst
// ---------------------------------------------------------------
__global__ void k_hist(const int* __restrict__ dst) {
    int e = blockIdx.x * blockDim.x + threadIdx.x;
    if (e < Ee) atomicAdd(&g_deg[dst[e]], 1);
}

// ---------------------------------------------------------------
// K2: order-free offset assignment: warp prefix + one atomicAdd/warp.
// ---------------------------------------------------------------
__global__ void k_off() {
    int n = blockIdx.x * blockDim.x + threadIdx.x;
    int lane = threadIdx.x & 31;
    int d = (n < Nn) ? g_deg[n] : 0;
    int pre = d;
#pragma unroll
    for (int o = 1; o < 32; o <<= 1) {
        int u = __shfl_up_sync(FULL, pre, o);
        if (lane >= o) pre += u;
    }
    int tot = __shfl_sync(FULL, pre, 31);
    int base = 0;
    if (lane == 31) base = atomicAdd(&g_ctr, tot);
    base = __shfl_sync(FULL, base, 31);
    int beg = base + pre - d;
    if (n < Nn) { g_beg[n] = beg; g_cur[n] = beg; }
}

// ---------------------------------------------------------------
// K3: scatter edge ids into per-dst contiguous ranges
// ---------------------------------------------------------------
__global__ void k_scatter(const int* __restrict__ dst) {
    int e = blockIdx.x * blockDim.x + threadIdx.x;
    if (e < Ee) {
        int pos = atomicAdd(&g_cur[dst[e]], 1);
        g_perm[pos] = e;
    }
}

// ---------------------------------------------------------------
// 9-shuffle reduction of 8 per-lane partials over the warp.
// Lane ends with full sum of value k(lane) = bitrev3(lane&7).
// Inverse map (source lane for k): SRC = {0,4,2,6,1,5,3,7}
// ---------------------------------------------------------------
__device__ __forceinline__ float reduce8_fast(float v[8], int lane) {
    bool b0 = lane & 1;
    float q0 = b0 ? v[4] : v[0], r0 = b0 ? v[0] : v[4];
    float q1 = b0 ? v[5] : v[1], r1 = b0 ? v[1] : v[5];
    float q2 = b0 ? v[6] : v[2], r2 = b0 ? v[2] : v[6];
    float q3 = b0 ? v[7] : v[3], r3 = b0 ? v[3] : v[7];
    q0 += __shfl_xor_sync(FULL, r0, 1);
    q1 += __shfl_xor_sync(FULL, r1, 1);
    q2 += __shfl_xor_sync(FULL, r2, 1);
    q3 += __shfl_xor_sync(FULL, r3, 1);
    bool b1 = lane & 2;
    float s0 = b1 ? q2 : q0, t0 = b1 ? q0 : q2;
    float s1 = b1 ? q3 : q1, t1 = b1 ? q1 : q3;
    s0 += __shfl_xor_sync(FULL, t0, 2);
    s1 += __shfl_xor_sync(FULL, t1, 2);
    bool b2 = lane & 4;
    float u0 = b2 ? s1 : s0, u1 = b2 ? s0 : s1;
    u0 += __shfl_xor_sync(FULL, u1, 4);
    u0 += __shfl_xor_sync(FULL, u0, 8);
    u0 += __shfl_xor_sync(FULL, u0, 16);
    return u0;
}

// ---------------------------------------------------------------
// K4 fused: role-split grid, software-pipelined at grid level.
// Per 128-node tile: 32 agg blocks (4 nodes each) then 8 gemm
// blocks (one head each).  Agg blocks release-increment g_done[tile];
// gemm blocks acquire-spin until all 32 arrived.  Dependencies point
// only at earlier blockIdx -> deadlock-free under in-order CTA issue.
// ---------------------------------------------------------------
__global__ __launch_bounds__(128) void k_fused(const float* __restrict__ ef,
                                               const float* __restrict__ nf,
                                               const float* __restrict__ Wr,
                                               const float* __restrict__ We,
                                               float* __restrict__ out) {
    __shared__ __align__(16) float smem_buf[12288];   // 48 KB (gemm staging)

    int bid = blockIdx.x;
    int tile = bid / BPT;
    int role = bid - tile * BPT;
    int t = threadIdx.x, lane = t & 31, w = t >> 5;

    if (role < 32) {
        // ================= AGG role: node = tile*128 + role*4 + w =========
        int n = tile * 128 + role * 4 + w;
        if (n < Nn) {
            float4 vv[Kk];
#pragma unroll
            for (int k = 0; k < Kk; ++k)
                vv[k] = ((const float4*)(g_v + k * Dd))[lane];

            float er_ln;
            {
                float4 x = ((const float4*)(nf + (size_t)n * Dd))[lane];
                float tk[Kk];
#pragma unroll
                for (int k = 0; k < Kk; ++k) {
                    float4 wk = ((const float4*)(Wr + k * Dd))[lane];
                    float s = x.x * wk.x;
                    s = fmaf(x.y, wk.y, s);
                    s = fmaf(x.z, wk.z, s);
                    s = fmaf(x.w, wk.w, s);
                    tk[k] = s;
                }
                er_ln = reduce8_fast(tk, lane);
            }

            float4 sl[Kk];
#pragma unroll
            for (int k = 0; k < Kk; ++k) sl[k] = make_float4(0.f, 0.f, 0.f, 0.f);
            float l_run = 0.f;

            int beg = g_beg[n];
            int end = beg + g_deg[n];
            constexpr int SRC[8] = {0, 4, 2, 6, 1, 5, 3, 7};

#define LOADE(idx, A, B, C) do {                                             \
        int eid = g_perm[(idx)];                                             \
        const float4* src = (const float4*)(ef + (size_t)eid * (Ll * Dd));   \
        A = __ldcs(src + lane);                                              \
        B = __ldcs(src + lane + 32);                                         \
        C = __ldcs(src + lane + 64);                                         \
    } while (0)

#define STEP(EA, EB, EC) do {                                                \
        float4 s4;                                                           \
        s4.x = EA.x + EB.x + EC.x;                                           \
        s4.y = EA.y + EB.y + EC.y;                                           \
        s4.z = EA.z + EB.z + EC.z;                                           \
        s4.w = EA.w + EB.w + EC.w;                                           \
        float tk[Kk];                                                        \
        _Pragma("unroll")                                                    \
        for (int k = 0; k < Kk; ++k) {                                       \
            float s = s4.x * vv[k].x;                                        \
            s = fmaf(s4.y, vv[k].y, s);                                      \
            s = fmaf(s4.z, vv[k].z, s);                                      \
            s = fmaf(s4.w, vv[k].w, s);                                      \
            tk[k] = s;                                                       \
        }                                                                    \
        float e = reduce8_fast(tk, lane) + er_ln;                            \
        e = (e > 0.f) ? e : 0.01f * e;                                       \
        float p = __expf(e);                                                 \
        l_run += p;                                                          \
        _Pragma("unroll")                                                    \
        for (int k = 0; k < Kk; ++k) {                                       \
            float pk = __shfl_sync(FULL, p, SRC[k]);                         \
            sl[k].x = fmaf(pk, s4.x, sl[k].x);                               \
            sl[k].y = fmaf(pk, s4.y, sl[k].y);                               \
            sl[k].z = fmaf(pk, s4.z, sl[k].z);                               \
            sl[k].w = fmaf(pk, s4.w, sl[k].w);                               \
        }                                                                    \
    } while (0)

            float4 A0, B0, C0, A1, B1, C1;
            if (beg < end)     LOADE(beg, A0, B0, C0);
            if (beg + 1 < end) LOADE(beg + 1, A1, B1, C1);

            int i = beg;
            while (i < end) {
                {
                    float4 ea = A0, eb = B0, ec = C0;
                    if (i + 2 < end) LOADE(i + 2, A0, B0, C0);
                    STEP(ea, eb, ec);
                }
                if (++i >= end) break;
                {
                    float4 ea = A1, eb = B1, ec = C1;
                    if (i + 2 < end) LOADE(i + 2, A1, B1, C1);
                    STEP(ea, eb, ec);
                }
                ++i;
            }
#undef LOADE
#undef STEP

            float inv = (l_run > 0.f) ? (1.f / l_run) : 0.f;
#pragma unroll
            for (int k = 0; k < Kk; ++k) {
                float ik = __shfl_sync(FULL, inv, SRC[k]) * (1.f / 3.f);
                float4 o;
                o.x = sl[k].x * ik; o.y = sl[k].y * ik;
                o.z = sl[k].z * ik; o.w = sl[k].w * ik;
                ((float4*)(g_S + ((size_t)n * Kk + k) * Dd))[lane] = o;
            }
        }
        // release: make S visible, then count this block done
        __syncthreads();
        __threadfence();
        if (t == 0) atomicAdd(&g_done[tile], 1u);
        return;
    }

    // ================= GEMM role: head kk over nodes [tile*128, +128) =====
    int kk = role - 32;
    int n0 = tile * 128;

    if (t == 0) {
        unsigned v;
        do {
            asm volatile("ld.acquire.gpu.u32 %0, [%1];"
                         : "=r"(v) : "l"(&g_done[tile]) : "memory");
            if (v >= 32u) break;
            __nanosleep(128);
        } while (true);
    }
    __syncthreads();

    float (*Ssd)[128] = (float (*)[128])smem_buf;            // [64][128]
    float (*Wsh)[64]  = (float (*)[64])(smem_buf + 8192);    // [64][64]

    int tx = t & 7, ty = t >> 3;       // 8 x 16
    int i0 = ty * 8, h0 = tx * 8;

    float acc[8][8];
#pragma unroll
    for (int a = 0; a < 8; ++a)
#pragma unroll
        for (int b = 0; b < 8; ++b) acc[a][b] = 0.f;

#pragma unroll
    for (int c = 0; c < 2; ++c) {
        __syncthreads();   // protect smem from previous chunk's compute

        // load W chunk: 1024 float4
#pragma unroll
        for (int j = 0; j < 8; ++j) {
            int wi = t + j * 128;
            int dd = wi >> 4;
            int hc = wi & 15;
            ((float4*)Wsh)[wi] =
                *((const float4*)(We + (size_t)(c * 64 + dd) * (Kk * Hh) + kk * Hh + hc * 4));
        }
        // load S chunk transposed: thread t owns node i = t
        {
            int n = n0 + t;
            if (n < Nn) {
                const float4* src =
                    (const float4*)(g_S + ((size_t)n * Kk + kk) * Dd + c * 64);
#pragma unroll
                for (int j = 0; j < 16; ++j) {
                    float4 v = src[j];
                    Ssd[j * 4 + 0][t] = v.x;
                    Ssd[j * 4 + 1][t] = v.y;
                    Ssd[j * 4 + 2][t] = v.z;
                    Ssd[j * 4 + 3][t] = v.w;
                }
            } else {
#pragma unroll
                for (int j = 0; j < 16; ++j) {
                    Ssd[j * 4 + 0][t] = 0.f;
                    Ssd[j * 4 + 1][t] = 0.f;
                    Ssd[j * 4 + 2][t] = 0.f;
                    Ssd[j * 4 + 3][t] = 0.f;
                }
            }
        }
        __syncthreads();

#pragma unroll 4
        for (int dd = 0; dd < 64; ++dd) {
            float4 a0 = *((const float4*)&Ssd[dd][i0]);
            float4 a1 = *((const float4*)&Ssd[dd][i0 + 4]);
            float4 b0 = *((const float4*)&Wsh[dd][h0]);
            float4 b1 = *((const float4*)&Wsh[dd][h0 + 4]);
            float av[8] = {a0.x, a0.y, a0.z, a0.w, a1.x, a1.y, a1.z, a1.w};
            float bv[8] = {b0.x, b0.y, b0.z, b0.w, b1.x, b1.y, b1.z, b1.w};
#pragma unroll
            for (int ii = 0; ii < 8; ++ii)
#pragma unroll
                for (int hh = 0; hh < 8; ++hh)
                    acc[ii][hh] = fmaf(av[ii], bv[hh], acc[ii][hh]);
        }
    }

#pragma unroll
    for (int ii = 0; ii < 8; ++ii) {
        int n = n0 + i0 + ii;
        if (n < Nn) {
            float* dst = out + (size_t)n * (Kk * Hh) + kk * Hh + h0;
            float4 v0 = make_float4(acc[ii][0], acc[ii][1], acc[ii][2], acc[ii][3]);
            float4 v1 = make_float4(acc[ii][4], acc[ii][5], acc[ii][6], acc[ii][7]);
            *((float4*)dst)       = v0;
            *((float4*)(dst + 4)) = v1;
        }
    }
}

// ---------------------------------------------------------------
extern "C" void kernel_launch(void* const* d_in, const int* in_sizes, int n_in,
                              void* d_out, int out_size) {
    const float* node_feat = (const float*)d_in[0];   // (N,128)
    const float* edge_feat = (const float*)d_in[1];   // (E,3,128)
    const float* W_enc     = (const float*)d_in[2];   // (128,512)
    const float* attn_l    = (const float*)d_in[3];   // (1,8,64)
    const float* W_r       = (const float*)d_in[4];   // (8,128)
    const int*   dst       = (const int*)  d_in[5];   // (E,)
    float*       out       = (float*)d_out;           // (N,8,64)

    k_prep<<<1, 1024>>>(W_enc, attn_l);
    k_hist<<<(Ee + 255) / 256, 256>>>(dst);
    k_off<<<(Nn + 255) / 256, 256>>>();
    k_scatter<<<(Ee + 255) / 256, 256>>>(dst);
    k_fused<<<TILES * BPT, 128>>>(edge_feat, node_feat, W_r, W_enc, out);
}